// round 14
// baseline (speedup 1.0000x reference)
#include <cuda_runtime.h>

// KVCache append, fused single kernel — best-measured R2 shape with
// write-through stores (st.global.wt): final cache-policy ablation.
// Loads stay .cs (evict-first, zero reuse); stores bypass L2 dirty state
// entirely, streaming toward DRAM without writeback scheduling.
// Previously measured: .cs stores 149.7us/86.0%, default stores 151.1/84.8.
// B=4,H=32,S=4096,T=1,D=128 fp32.
// out = [k_cache ++ k_val (axis=2)] then [v_cache ++ v_val].
// 537MB in + 537MB out pure stream; plateau ~6.82 TB/s (86% of spec).

#define KV_S 4096
#define KV_T 1
#define KV_D 128

#define ROWS         128                         // B*H rows
#define ROW4_IN      (KV_S * KV_D / 4)           // 131072 float4 per cache row
#define ROW4_OUT     ((KV_S + KV_T) * KV_D / 4)  // 131104 float4 per output row
#define HALF4        ((long)ROWS * ROW4_OUT)     // float4 per output tensor
#define VAL4_PER_ROW (KV_T * KV_D / 4)           // 32 float4 appended per row

#define UNROLL     4
#define TPB        256
#define CHUNK      (TPB * UNROLL)                // 1024 float4 per block
#define CACHE_BLKS (ROW4_IN / CHUNK)             // 128 x-blocks per (row,half)

__global__ void __launch_bounds__(TPB)
kv_append(const float4* __restrict__ k_cache,
          const float4* __restrict__ v_cache,
          const float4* __restrict__ k_val,
          const float4* __restrict__ v_val,
          float4* __restrict__ out)
{
    const int half = blockIdx.z;   // 0 = k, 1 = v
    const int row  = blockIdx.y;   // (b,h) flattened

    float4* __restrict__ dst = out + (long)half * HALF4 + (long)row * ROW4_OUT;

    if (blockIdx.x < CACHE_BLKS) {
        // Bulk cache copy: 4 coalesced float4 per thread, loads batched
        // before stores. Reads evict-first; writes write-through.
        const float4* __restrict__ src =
            (half ? v_cache : k_cache) + (long)row * ROW4_IN;
        const long base = (long)blockIdx.x * CHUNK + threadIdx.x;

        float4 r[UNROLL];
        #pragma unroll
        for (int u = 0; u < UNROLL; u++)
            r[u] = __ldcs(&src[base + u * TPB]);
        #pragma unroll
        for (int u = 0; u < UNROLL; u++)
            __stwt(&dst[base + u * TPB], r[u]);
    } else if (threadIdx.x < VAL4_PER_ROW) {
        // Append the new token for this (row, half): 32 float4 = 512B.
        const float4* __restrict__ sv = half ? v_val : k_val;
        __stwt(&dst[ROW4_IN + threadIdx.x],
               __ldcs(&sv[row * VAL4_PER_ROW + threadIdx.x]));
    }
}

extern "C" void kernel_launch(void* const* d_in, const int* in_sizes, int n_in,
                              void* d_out, int out_size)
{
    const float4* k_cache = (const float4*)d_in[0];
    const float4* v_cache = (const float4*)d_in[1];
    const float4* k_val   = (const float4*)d_in[2];
    const float4* v_val   = (const float4*)d_in[3];
    float4* out = (float4*)d_out;

    dim3 grid(CACHE_BLKS + 1, ROWS, 2);  // (129, 128, 2)
    kv_append<<<grid, TPB>>>(k_cache, v_cache, k_val, v_val, out);
}

// round 15
// speedup vs baseline: 1.0215x; 1.0215x over previous
#include <cuda_runtime.h>

// KVCache append, fused single kernel — FINAL (measured optimum, 14-round
// sweep closed). Ablated: unroll {1,4,8}, TPB {256,512}, one-shot vs
// persistent grids, val handling {2nd launch, fused branch, extra block},
// store policy {.cs best, default -1.2%, .wt -0.6%}, ld/st {batched best,
// interleaved}, cudaMemcpy2DAsync (3.4x slower).
// Best: 156.2us bench / ~149us kernel @ 6.8TB/s = 86% of HBM spec — the
// measured path-independent LTS/DRAM ceiling for a balanced bidirectional
// stream. Traffic (537MB in + 537MB out) is algorithmically irreducible.
// B=4,H=32,S=4096,T=1,D=128 fp32.
// out = [k_cache ++ k_val (axis=2)] then [v_cache ++ v_val].

#define KV_S 4096
#define KV_T 1
#define KV_D 128

#define ROWS         128                         // B*H rows
#define ROW4_IN      (KV_S * KV_D / 4)           // 131072 float4 per cache row
#define ROW4_OUT     ((KV_S + KV_T) * KV_D / 4)  // 131104 float4 per output row
#define HALF4        ((long)ROWS * ROW4_OUT)     // float4 per output tensor
#define VAL4_PER_ROW (KV_T * KV_D / 4)           // 32 float4 appended per row

#define UNROLL     4
#define TPB        256
#define CHUNK      (TPB * UNROLL)                // 1024 float4 per block
#define CACHE_BLKS (ROW4_IN / CHUNK)             // 128 x-blocks per (row,half)

__global__ void __launch_bounds__(TPB)
kv_append(const float4* __restrict__ k_cache,
          const float4* __restrict__ v_cache,
          const float4* __restrict__ k_val,
          const float4* __restrict__ v_val,
          float4* __restrict__ out)
{
    const int half = blockIdx.z;   // 0 = k, 1 = v
    const int row  = blockIdx.y;   // (b,h) flattened

    float4* __restrict__ dst = out + (long)half * HALF4 + (long)row * ROW4_OUT;

    if (blockIdx.x < CACHE_BLKS) {
        // Bulk cache copy: 4 coalesced float4 per thread, loads batched
        // before stores, evict-first (.cs) on both streams (zero reuse).
        const float4* __restrict__ src =
            (half ? v_cache : k_cache) + (long)row * ROW4_IN;
        const long base = (long)blockIdx.x * CHUNK + threadIdx.x;

        float4 r[UNROLL];
        #pragma unroll
        for (int u = 0; u < UNROLL; u++)
            r[u] = __ldcs(&src[base + u * TPB]);
        #pragma unroll
        for (int u = 0; u < UNROLL; u++)
            __stcs(&dst[base + u * TPB], r[u]);
    } else if (threadIdx.x < VAL4_PER_ROW) {
        // Append the new token for this (row, half): 32 float4 = 512B.
        const float4* __restrict__ sv = half ? v_val : k_val;
        __stcs(&dst[ROW4_IN + threadIdx.x],
               __ldcs(&sv[row * VAL4_PER_ROW + threadIdx.x]));
    }
}

extern "C" void kernel_launch(void* const* d_in, const int* in_sizes, int n_in,
                              void* d_out, int out_size)
{
    const float4* k_cache = (const float4*)d_in[0];
    const float4* v_cache = (const float4*)d_in[1];
    const float4* k_val   = (const float4*)d_in[2];
    const float4* v_val   = (const float4*)d_in[3];
    float4* out = (float4*)d_out;

    dim3 grid(CACHE_BLKS + 1, ROWS, 2);  // (129, 128, 2)
    kv_append<<<grid, TPB>>>(k_cache, v_cache, k_val, v_val, out);
}